// round 5
// baseline (speedup 1.0000x reference)
#include <cuda_runtime.h>

#define N_ZQ   2097152   // 8*64*64*64
#define N_IDX  32768
#define K_ROWS 8192
#define D_DIM  64
#define NB     512
#define NT     256
#define N_F4   (N_ZQ / 4)    // 524288 = NB*NT*4 exactly

// Persistent scratch. g_arrive is a monotone ticket counter: since
// 2^32 % NB == 0, generation arithmetic wraps cleanly across unlimited
// graph replays — no reset needed, fully deterministic.
__device__ unsigned long long g_amin[NB];
__device__ double g_losspart[NB];
__device__ unsigned int g_arrive;

__device__ __forceinline__ unsigned ld_cv_u32(const unsigned* p) {
    unsigned v;
    asm volatile("ld.global.cv.u32 %0, [%1];" : "=r"(v) : "l"(p));
    return v;
}

// Sense-free grid barrier via monotone ticket. Every block arrives once;
// if `wait`, spin until this generation's NB arrivals complete.
__device__ __forceinline__ void grid_barrier(bool wait) {
    __threadfence();
    __syncthreads();
    if (threadIdx.x == 0) {
        unsigned t = atomicAdd(&g_arrive, 1u);
        unsigned tgt = (t & ~(unsigned)(NB - 1)) + NB;   // (gen+1)*NB, wrap-safe
        if (wait) {
            while ((int)(ld_cv_u32(&g_arrive) - tgt) < 0) { }
        }
    }
    if (wait) {
        __syncthreads();
        __threadfence();
    }
}

__global__ void __launch_bounds__(NT, 4)
k_fused(const float* __restrict__ in, const float* __restrict__ book,
        float* __restrict__ out, int out_size) {
    __shared__ unsigned long long s[NT];
    __shared__ float sbk[D_DIM];
    __shared__ float swr[8];

    int t = threadIdx.x;
    int b = blockIdx.x;

    // ---------------- Phase 1: cooperative book argmin -------------------
    // One float4 per thread covers the whole book (NB*NT == 8192 rows * 16
    // float4s). 16 consecutive lanes share a row -> shfl-xor butterfly.
    {
        int f = b * NT + t;                       // book float4 id
        const float4* bk4 = reinterpret_cast<const float4*>(book);
        float4 v = bk4[f];
        float acc = v.x * v.x;
        acc = fmaf(v.y, v.y, acc);
        acc = fmaf(v.z, v.z, acc);
        acc = fmaf(v.w, v.w, acc);
#pragma unroll
        for (int off = 1; off < 16; off <<= 1)
            acc += __shfl_xor_sync(0xffffffffu, acc, off);
        int row = f >> 4;
        // positive-float bits are monotone: u64 min = (min norm, lowest row)
        unsigned long long key =
            ((unsigned long long)__float_as_uint(acc) << 32) | (unsigned)row;
        s[t] = key;
        __syncthreads();
#pragma unroll
        for (int off = NT / 2; off > 0; off >>= 1) {
            if (t < off) {
                unsigned long long o = s[t + off];
                if (o < s[t]) s[t] = o;
            }
            __syncthreads();
        }
        if (t == 0) g_amin[b] = s[0];
    }

    grid_barrier(true);   // all blocks wait: g_amin fully published

    // ---------------- Phase 2: global argmin + fused streaming -----------
    {
        unsigned long long a = g_amin[t];
        unsigned long long c = g_amin[t + NT];
        s[t] = (c < a) ? c : a;
    }
    __syncthreads();
#pragma unroll
    for (int off = NT / 2; off > 0; off >>= 1) {
        if (t < off) {
            unsigned long long o = s[t + off];
            if (o < s[t]) s[t] = o;
        }
        __syncthreads();
    }
    int kmin = (int)(s[0] & 0xffffffffu);
    if (t < D_DIM) sbk[t] = book[(size_t)kmin * D_DIM + t];
    __syncthreads();

    int gtid = b * NT + t;
    const int stride = NB * NT;
    const float4* in4  = reinterpret_cast<const float4*>(in);
    float4*       out4 = reinterpret_cast<float4*>(out);

    float lsum = 0.0f;
#pragma unroll
    for (int k = 0; k < 4; ++k) {
        int j = gtid + k * stride;
        float4 x = in4[j];
        int w0 = (j << 2) & 63;                 // w index of x.x
        float d0 = sbk[w0]     - x.x;
        float d1 = sbk[w0 + 1] - x.y;
        float d2 = sbk[w0 + 2] - x.z;
        float d3 = sbk[w0 + 3] - x.w;
        lsum = fmaf(d0, d0, lsum);
        lsum = fmaf(d1, d1, lsum);
        lsum = fmaf(d2, d2, lsum);
        lsum = fmaf(d3, d3, lsum);
        // z_q flat value depends only on (4j>>12)&63 (raw-reshape quirk)
        float v = sbk[(j >> 10) & 63];
        out4[j] = make_float4(v, v, v, v);
    }

    // idx section: constant argmin index as float, vectorized
    if (out_size >= N_ZQ + N_IDX && gtid < N_IDX / 4) {
        float fk = (float)kmin;
        out4[N_ZQ / 4 + gtid] = make_float4(fk, fk, fk, fk);
    }

    // block loss partial
#pragma unroll
    for (int off = 16; off > 0; off >>= 1)
        lsum += __shfl_down_sync(0xffffffffu, lsum, off);
    if ((t & 31) == 0) swr[t >> 5] = lsum;
    __syncthreads();
    if (t == 0) {
        double ds = 0.0;
#pragma unroll
        for (int i = 0; i < 8; ++i) ds += (double)swr[i];
        g_losspart[b] = ds;
    }

    // ---------------- Phase 3: loss finalize (block 0 only waits) --------
    grid_barrier(b == 0);
    if (b == 0) {
        __shared__ double sd[NT];
        sd[t] = g_losspart[t] + g_losspart[t + NT];
        __syncthreads();
#pragma unroll
        for (int off = NT / 2; off > 0; off >>= 1) {
            if (t < off) sd[t] += sd[t + off];
            __syncthreads();
        }
        if (t == 0 && out_size >= N_ZQ + N_IDX + 1)
            out[N_ZQ + N_IDX] = (float)(1.25 * sd[0] / (double)N_ZQ);
    }
}

extern "C" void kernel_launch(void* const* d_in, const int* in_sizes, int n_in,
                              void* d_out, int out_size) {
    const float* input = (const float*)d_in[0];
    const float* book  = (const float*)d_in[1];
    if (n_in >= 2 && in_sizes[0] == K_ROWS * D_DIM && in_sizes[1] == N_ZQ) {
        const float* tmp = input; input = book; book = tmp;
    }
    k_fused<<<NB, NT>>>(input, book, (float*)d_out, out_size);
}